// round 6
// baseline (speedup 1.0000x reference)
#include <cuda_runtime.h>
#include <cstdint>

typedef unsigned long long ull;

#define NROWS   32768      // rows per input tensor (8*64*64)
#define DIMD    256        // feature dim
#define KC      1024       // codebook size

// output layout (float32, tuple-concat order)
#define ESZ      8388608ull    // one ste block (NROWS*DIMD)
#define DSZ      33554432ull   // one dist block (NROWS*KC)
#define OFF_DIFF 33554432ull   // after 4 ste blocks
#define OFF_IND  33554436ull   // after 4 diff scalars
#define OFF_DIST 33685508ull   // after 4 ind blocks (4*32768)

// scratch (static device globals — no allocations)
__device__ __align__(16) ull    g_keys[2 * NROWS];
__device__ __align__(16) float  g_xsq[2 * NROWS];
__device__ __align__(16) float  g_esq[KC];
__device__ __align__(16) float  g_embT[KC * DIMD];
__device__ double g_diff[2];

__device__ __forceinline__ ull dup2(float x) {
    ull r; asm("mov.b64 %0, {%1, %1};" : "=l"(r) : "f"(x)); return r;
}
__device__ __forceinline__ ull fma2(ull a, ull b, ull c) {
    ull d; asm("fma.rn.f32x2 %0, %1, %2, %3;" : "=l"(d) : "l"(a), "l"(b), "l"(c)); return d;
}

union F4U { float4 f; ull u[2]; float s[4]; };
union ULF { ull u; float2 f; };

// ---------------------------------------------------------------- init
__global__ void k_init() {
    int i = blockIdx.x * blockDim.x + threadIdx.x;   // 65536 threads exactly
    g_keys[i] = ~0ull;
    if (i < 2) g_diff[i] = 0.0;
}

// ------------------------------------------------- per-row ||x||^2
// XLA-style row-reduce: per-lane strided (lane+32j) mul.rn+add.rn partials
// (no fma contraction), then shfl-DOWN tree; lane 0 holds the result.
__global__ void k_prep_rows(const float* __restrict__ hr, const float* __restrict__ lr) {
    int w    = blockIdx.x * (blockDim.x >> 5) + (threadIdx.x >> 5);   // 16384 warps
    int lane = threadIdx.x & 31;
#pragma unroll
    for (int i = 0; i < 4; i++) {
        int row = w + i * 16384;                                      // 0..65535
        const float* x = (row >= NROWS) ? (lr + (size_t)(row - NROWS) * DIMD)
                                        : (hr + (size_t)row * DIMD);
        float s = 0.f;
#pragma unroll
        for (int j = 0; j < 8; j++) {
            float v = x[lane + (j << 5)];
            s = __fadd_rn(s, __fmul_rn(v, v));
        }
#pragma unroll
        for (int o = 16; o > 0; o >>= 1)
            s = __fadd_rn(s, __shfl_down_sync(0xffffffffu, s, o));
        if (lane == 0) g_xsq[row] = s;
    }
}

// ----------------------------- per-code ||e||^2 + transposed codebook
// Column-reduce of [256,1024] over rows: lane partial over d=lane+32i
// (mul.rn+add.rn, ascending i), shfl-down tree. Strided reads double as
// the embT transpose copy.
__global__ void k_prep_embed(const float* __restrict__ embed) {
    int warp = blockIdx.x * (blockDim.x >> 5) + (threadIdx.x >> 5);   // 1024 warps
    int lane = threadIdx.x & 31;
    int c    = warp;                                                  // column 0..1023
    float s = 0.f;
#pragma unroll
    for (int i = 0; i < 8; i++) {
        int d = lane + (i << 5);
        float v = embed[(size_t)d * KC + c];
        g_embT[(size_t)c * DIMD + d] = v;
        s = __fadd_rn(s, __fmul_rn(v, v));
    }
#pragma unroll
    for (int o = 16; o > 0; o >>= 1)
        s = __fadd_rn(s, __shfl_down_sync(0xffffffffu, s, o));
    if (lane == 0) g_esq[c] = s;
}

// ------------------------------------------------ fused GEMM + dist + argmin
// 128x128 tile, BK=16, 256 threads, 8x8 micro-tile, fp32x2 packed along M.
// Single fma chain per (row,col), k ascending -> matches SGEMM rounding.
__global__ __launch_bounds__(256, 2) void k_gemm(
    const float* __restrict__ hr, const float* __restrict__ lr,
    const float* __restrict__ embed, float* __restrict__ out)
{
    __shared__ float As[16][132];   // transposed, padded (conflict-free)
    __shared__ float Bs[16][128];
    __shared__ ull   skey[128];

    const int z       = blockIdx.z;
    const float* A    = z ? lr : hr;
    const int rowBase = blockIdx.y << 7;
    const int colBase = blockIdx.x << 7;
    const int tid     = threadIdx.x;
    const int tx      = tid & 15, ty = tid >> 4;

    ull acc[4][8];
#pragma unroll
    for (int m = 0; m < 4; m++)
#pragma unroll
        for (int j = 0; j < 8; j++) acc[m][j] = 0ull;

    if (tid < 128) skey[tid] = ~0ull;

    for (int kb = 0; kb < DIMD; kb += 16) {
#pragma unroll
        for (int i = 0; i < 2; i++) {          // A tile: 128 rows x 16, store transposed
            int f4 = tid + (i << 8);
            int r = f4 >> 2, kq = (f4 & 3) << 2;
            float4 v = *(const float4*)(A + (size_t)(rowBase + r) * DIMD + kb + kq);
            As[kq + 0][r] = v.x; As[kq + 1][r] = v.y;
            As[kq + 2][r] = v.z; As[kq + 3][r] = v.w;
        }
#pragma unroll
        for (int i = 0; i < 2; i++) {          // B tile: 16 x 128
            int f4 = tid + (i << 8);
            int d = f4 >> 5, c = (f4 & 31) << 2;
            *(float4*)&Bs[d][c] = *(const float4*)(embed + (size_t)(kb + d) * KC + colBase + c);
        }
        __syncthreads();
#pragma unroll
        for (int k = 0; k < 16; k++) {
            F4U a0, a1, b0, b1;
            a0.f = *(const float4*)&As[k][(ty << 3)];
            a1.f = *(const float4*)&As[k][(ty << 3) + 4];
            b0.f = *(const float4*)&Bs[k][(tx << 3)];
            b1.f = *(const float4*)&Bs[k][(tx << 3) + 4];
            ull ap[4] = { a0.u[0], a0.u[1], a1.u[0], a1.u[1] };   // row pairs (free pack)
            float bv[8] = { b0.s[0], b0.s[1], b0.s[2], b0.s[3],
                            b1.s[0], b1.s[1], b1.s[2], b1.s[3] };
#pragma unroll
            for (int j = 0; j < 8; j++) {
                ull bd = dup2(bv[j]);
#pragma unroll
                for (int m = 0; m < 4; m++) acc[m][j] = fma2(ap[m], bd, acc[m][j]);
            }
        }
        __syncthreads();
    }

    // epilogue: dist = (xsq - 2*S) + esq   [EXACT reference rounding order],
    // write both dup dist blocks, packed argmin (lowest index on bitwise ties).
    float esqv[8];
#pragma unroll
    for (int j = 0; j < 8; j++) esqv[j] = g_esq[colBase + (tx << 3) + j];

#pragma unroll
    for (int m = 0; m < 4; m++) {
#pragma unroll
        for (int h = 0; h < 2; h++) {
            int r    = (ty << 3) + (m << 1) + h;
            int grow = rowBase + r;
            float xs = g_xsq[(size_t)z * NROWS + grow];
            float v[8];
            ull best = ~0ull;
#pragma unroll
            for (int j = 0; j < 8; j++) {
                ULF q; q.u = acc[m][j];
                float sdot = h ? q.f.y : q.f.x;
                float dv = __fadd_rn(__fsub_rn(xs, __fmul_rn(2.f, sdot)), esqv[j]);
                v[j] = dv;
                ull key = ((ull)__float_as_uint(dv) << 32)
                        | (unsigned)(colBase + (tx << 3) + j);
                if (key < best) best = key;
            }
            atomicMin(&skey[r], best);
            size_t o1 = OFF_DIST + (size_t)z * DSZ + (size_t)grow * KC + colBase + (tx << 3);
            size_t o2 = o1 + 2 * DSZ;
            float4 s0 = make_float4(v[0], v[1], v[2], v[3]);
            float4 s1 = make_float4(v[4], v[5], v[6], v[7]);
            *(float4*)(out + o1)     = s0; *(float4*)(out + o1 + 4) = s1;
            *(float4*)(out + o2)     = s0; *(float4*)(out + o2 + 4) = s1;
        }
    }
    __syncthreads();
    if (tid < 128)
        atomicMin(&g_keys[(size_t)z * NROWS + rowBase + tid], skey[tid]);
}

// ------------------------------------ gather: ste = x + (q - x), ind, diff
__global__ void k_gather(const float* __restrict__ hr, const float* __restrict__ lr,
                         float* __restrict__ out)
{
    int w    = blockIdx.x * (blockDim.x >> 5) + (threadIdx.x >> 5);  // 65536 warps
    int lane = threadIdx.x & 31;
    int z    = w >> 15;
    int row  = w & 32767;
    const float* x = (z ? lr : hr) + (size_t)row * DIMD;
    ull key = g_keys[w];
    unsigned ind = (unsigned)(key & 0xffffffffull);
    const float* q = g_embT + (size_t)ind * DIMD;
    float* s1 = out + (size_t)z * ESZ + (size_t)row * DIMD;
    float* s2 = s1 + 2 * ESZ;
    float acc = 0.f;
#pragma unroll
    for (int j = 0; j < 8; j++) {
        int c  = lane + (j << 5);
        float xv = x[c];
        float qv = q[c];
        float d  = __fsub_rn(qv, xv);         // reference: quantize - input
        float sv = __fadd_rn(xv, d);          // reference STE: x + (q - x), bitwise
        acc = fmaf(d, d, acc);
        s1[c] = sv; s2[c] = sv;
    }
#pragma unroll
    for (int o = 16; o > 0; o >>= 1) acc += __shfl_xor_sync(0xffffffffu, acc, o);
    if (lane == 0) {
        atomicAdd(&g_diff[z], (double)acc);
        out[OFF_IND + (size_t)z * NROWS + row]            = (float)ind;
        out[OFF_IND + 65536ull + (size_t)z * NROWS + row] = (float)ind;
    }
}

// --------------------------------------------------------------- finalize
__global__ void k_final(float* __restrict__ out) {
    int t = threadIdx.x;
    if (t < 4) out[OFF_DIFF + t] = (float)(g_diff[t & 1] / 8388608.0);
}

extern "C" void kernel_launch(void* const* d_in, const int* in_sizes, int n_in,
                              void* d_out, int out_size)
{
    const float* hr = (const float*)d_in[0];
    const float* lr = (const float*)d_in[1];
    const float* em = (const float*)d_in[2];
    float* out = (float*)d_out;

    k_init<<<256, 256>>>();
    k_prep_rows<<<2048, 256>>>(hr, lr);
    k_prep_embed<<<128, 256>>>(em);
    dim3 g(KC / 128, NROWS / 128, 2);          // 8 x 256 x 2  (colTile fastest -> A reuse in L2)
    k_gemm<<<g, 256>>>(hr, lr, em, out);
    k_gather<<<8192, 256>>>(hr, lr, out);
    k_final<<<1, 32>>>(out);
}